// round 6
// baseline (speedup 1.0000x reference)
#include <cuda_runtime.h>

// NSE_layer: fused NSE residual + BC-mask outputs, 2048x2048 grid.
// Output flat concat: loss (3,3,2046,2046) | mask (1,3,2048,2048) | gbv (2,1,3,2048,2048)
// Structure: flags ∥ mask(flag-free) ∥ loss(flag-free)  ->  edge_fix (X=0/1/2046/2047)

#define GNX 2048
#define GNY 2048
#define NNX 2046

__device__ unsigned char g_row_in[GNY];
__device__ unsigned char g_row_out[GNY];

// Warp-per-row flags.
__global__ __launch_bounds__(256)
void row_flags_kernel(const int* __restrict__ lay) {
    int warp = threadIdx.x >> 5;
    int lane = threadIdx.x & 31;
    int y = blockIdx.x * 8 + warp;
    const int4* row = (const int4*)(lay + (size_t)y * GNX);
    int f = 0;
    #pragma unroll
    for (int i = 0; i < 16; i++) {
        int4 L = __ldg(row + lane + 32 * i);
        f |= ((L.x == 1) | (L.y == 1) | (L.z == 1) | (L.w == 1));
        f |= ((L.x == 3) | (L.y == 3) | (L.z == 3) | (L.w == 3)) << 1;
    }
    f = __reduce_or_sync(0xffffffffu, f);
    if (lane == 0) {
        g_row_in[y]  = (unsigned char)(f & 1);
        g_row_out[y] = (unsigned char)((f >> 1) & 1);
    }
}

// ---------------- mask + gbv kernel (flag-free) ----------------
__global__ __launch_bounds__(256)
void mask_kernel(const int* __restrict__ lay,
                 float* __restrict__ out_mask,
                 float* __restrict__ out_gbv)
{
    const size_t NP = (size_t)GNX * GNY;
    int k = blockIdx.x * 32 + threadIdx.x;      // 0..511
    int Y = blockIdx.y * 8  + threadIdx.y;      // 0..2047
    size_t idx = (size_t)Y * GNX + 4 * k;

    int4 L4 = __ldg((const int4*)(lay + idx));
    int Ls[4] = {L4.x, L4.y, L4.z, L4.w};

    float mk[4], gb[4];
    #pragma unroll
    for (int j = 0; j < 4; j++) {
        int L = Ls[j];
        float base = (L == 2) ? 0.f : 1.f;
        float keep = (L > 3) ? 0.f : 1.f;
        float code = (L > 3) ? (float)L : 0.f;
        gb[j] = base;
        mk[j] = base * keep + code;
    }
    float4 mkv = make_float4(mk[0], mk[1], mk[2], mk[3]);
    float4 gbv = make_float4(gb[0], gb[1], gb[2], gb[3]);
    float4 z   = make_float4(0.f, 0.f, 0.f, 0.f);

    __stcs((float4*)(out_mask + 0 * NP + idx), mkv);
    __stcs((float4*)(out_mask + 1 * NP + idx), mkv);
    __stcs((float4*)(out_mask + 2 * NP + idx), mkv);
    __stcs((float4*)(out_gbv + 0 * NP + idx), gbv);
    __stcs((float4*)(out_gbv + 1 * NP + idx), gbv);
    __stcs((float4*)(out_gbv + 2 * NP + idx), gbv);
    __stcs((float4*)(out_gbv + 3 * NP + idx), z);
    __stcs((float4*)(out_gbv + 4 * NP + idx), z);
    __stcs((float4*)(out_gbv + 5 * NP + idx), z);
}

// ---------------- loss kernel (flag-free) ----------------
__device__ __forceinline__ void load_uvp_row_nf(
    const float* __restrict__ f0, const float* __restrict__ f1,
    const float* __restrict__ f2, const int* __restrict__ lay,
    int r, int xv, bool tail,
    float* u, float* v, float* p, int* lf_out)
{
    size_t off = (size_t)r * GNX + xv;
    float4 ua = __ldg((const float4*)(f0 + off));
    float4 va = __ldg((const float4*)(f1 + off));
    float4 pa = __ldg((const float4*)(f2 + off));
    int4   la = __ldg((const int4*)(lay + off));
    float u4 = 0.f, u5 = 0.f, v4 = 0.f, v5 = 0.f, p4 = 0.f, p5 = 0.f;
    int   l4 = 0, l5 = 0;
    if (!tail) {
        float4 ub = __ldg((const float4*)(f0 + off + 4));
        float4 vb = __ldg((const float4*)(f1 + off + 4));
        float4 pb = __ldg((const float4*)(f2 + off + 4));
        int4   lb = __ldg((const int4*)(lay + off + 4));
        u4 = ub.x; u5 = ub.y; v4 = vb.x; v5 = vb.y; p4 = pb.x; p5 = pb.y;
        l4 = lb.x; l5 = lb.y;
    }
    float uf[6] = {ua.x, ua.y, ua.z, ua.w, u4, u5};
    float vf[6] = {va.x, va.y, va.z, va.w, v4, v5};
    float pf[6] = {pa.x, pa.y, pa.z, pa.w, p4, p5};
    int   lf[6] = {la.x, la.y, la.z, la.w, l4, l5};
    #pragma unroll
    for (int i = 0; i < 6; i++) {
        float m = (lf[i] == 2) ? 0.f : 1.f;
        u[i] = uf[i] * m;
        v[i] = vf[i] * m;
        p[i] = pf[i] * m;
        if (lf_out) lf_out[i] = lf[i];
    }
}

__global__ __launch_bounds__(256)
void loss_kernel(const int* __restrict__ lay,
                 const float* __restrict__ f0,
                 const float* __restrict__ f1,
                 const float* __restrict__ f2,
                 float* __restrict__ out_loss)
{
    const size_t NN = (size_t)NNX * NNX;
    int k = blockIdx.x * 32 + threadIdx.x;        // 0..511
    int Y = blockIdx.y * 8  + threadIdx.y + 1;    // 1..2048
    if (Y > GNY - 2) return;
    bool tail = (k == 511);
    int  xv   = 4 * k;

    float un[6], vn[6], pn[6];
    float uc[6], vc[6], pc[6];
    float us[6], vs[6], ps[6];
    int   lc[6];
    load_uvp_row_nf(f0, f1, f2, lay, Y - 1, xv, tail, un, vn, pn, (int*)0);
    load_uvp_row_nf(f0, f1, f2, lay, Y,     xv, tail, uc, vc, pc, lc);
    load_uvp_row_nf(f0, f1, f2, lay, Y + 1, xv, tail, us, vs, ps, (int*)0);

    const float h     = (float)(0.1 / 2047.0);
    const float inv_h = 1.0f / h;
    const float nu_h2 = 0.05f / (h * h);

    float r0[4], r1[4], r2[4];
    #pragma unroll
    for (int j = 0; j < 4; j++) {
        int   L   = lc[j + 1];
        float Uc  = uc[j + 1], Vc = vc[j + 1];
        float dxu = 0.5f * (uc[j + 2] - uc[j]);
        float dyu = 0.5f * (us[j + 1] - un[j + 1]);
        float dxv = 0.5f * (vc[j + 2] - vc[j]);
        float dyv = 0.5f * (vs[j + 1] - vn[j + 1]);
        float lapu = un[j + 1] + us[j + 1] + uc[j] + uc[j + 2] - 4.0f * Uc;
        float lapv = vn[j + 1] + vs[j + 1] + vc[j] + vc[j + 2] - 4.0f * Vc;
        float cont = dxu * inv_h + dyv * inv_h;

        bool fx  = (L == 4) | (L == 8)  | (L == 11);
        bool bx  = (L == 6) | (L == 9)  | (L == 10);
        bool fy  = (L == 7) | (L == 10) | (L == 11);
        bool by  = (L == 5) | (L == 8)  | (L == 9);
        float dpx = fx ? (pc[j + 2] - pc[j + 1]) : (bx ? (pc[j + 1] - pc[j]) : 0.5f * (pc[j + 2] - pc[j]));
        float dpy = fy ? (pn[j + 1] - pc[j + 1]) : (by ? (pc[j + 1] - ps[j + 1]) : 0.5f * (ps[j + 1] - pn[j + 1]));

        float mu = Uc * dxu * inv_h + Vc * dyu * inv_h + dpx * inv_h - lapu * nu_h2;
        float mv = Uc * dxv * inv_h + Vc * dyv * inv_h + dpy * inv_h - lapv * nu_h2;

        float m = (L == 2) ? 0.f : 1.f;
        r0[j] = m * mu; r1[j] = m * mv; r2[j] = m * cont;
    }

    size_t li = (size_t)(Y - 1) * NNX + 4 * k;    // even -> float2-aligned
    float2 a0 = make_float2(r0[0], r0[1]), b0 = make_float2(r0[2], r0[3]);
    float2 a1 = make_float2(r1[0], r1[1]), b1 = make_float2(r1[2], r1[3]);
    float2 a2 = make_float2(r2[0], r2[1]), b2 = make_float2(r2[2], r2[3]);
    #pragma unroll
    for (int rep = 0; rep < 3; rep++) {
        float* p0 = out_loss + (size_t)(0 * 3 + rep) * NN + li;
        float* p1 = out_loss + (size_t)(1 * 3 + rep) * NN + li;
        float* p2 = out_loss + (size_t)(2 * 3 + rep) * NN + li;
        __stcs((float2*)p0, a0);
        __stcs((float2*)p1, a1);
        __stcs((float2*)p2, a2);
        if (!tail) {
            __stcs((float2*)(p0 + 2), b0);
            __stcs((float2*)(p1 + 2), b1);
            __stcs((float2*)(p2 + 2), b2);
        }
    }
}

// ---------------- edge fix: rewrite all flag-dependent outputs ----------------
// tasks: 0 = mask/gbv @ X=0, 1 = mask/gbv @ X=2047, 2 = loss @ X=1, 3 = loss @ X=2046
__global__ __launch_bounds__(256)
void edge_fix_kernel(const int* __restrict__ lay,
                     const float* __restrict__ f0,
                     const float* __restrict__ f1,
                     const float* __restrict__ f2,
                     float* __restrict__ out_loss,
                     float* __restrict__ out_mask,
                     float* __restrict__ out_gbv)
{
    const size_t NP = (size_t)GNX * GNY;
    const size_t NN = (size_t)NNX * NNX;
    int t = blockIdx.x * blockDim.x + threadIdx.x;   // 0..8191
    int task = t & 3;
    int Y = t >> 2;
    if (Y >= GNY) return;

    if (task < 2) {
        int X = task ? (GNX - 1) : 0;
        size_t idx = (size_t)Y * GNX + X;
        int L = __ldg(lay + idx);
        float base = (L == 2) ? 0.f : 1.f;
        float gb0 = base, gb1 = base, gb2 = base, gv0 = 0.f;
        if (X == 0 && g_row_in[Y])        { gb0 = 0.f; gb1 = 0.f; gv0 = 3.f; }
        if (X == GNX - 1 && g_row_out[Y]) { gb2 = 0.f; }
        float keep = (L > 3) ? 0.f : 1.f;
        float code = (L > 3) ? (float)L : 0.f;
        out_mask[0 * NP + idx] = gb0 * keep + code;
        out_mask[1 * NP + idx] = gb1 * keep + code;
        out_mask[2 * NP + idx] = gb2 * keep + code;
        out_gbv[0 * NP + idx] = gb0;
        out_gbv[1 * NP + idx] = gb1;
        out_gbv[2 * NP + idx] = gb2;
        out_gbv[3 * NP + idx] = gv0;
    } else {
        if (Y < 1 || Y > GNY - 2) return;
        int X = (task == 2) ? 1 : (GNX - 2);

        float u[3][3], v[3][3], p[3][3];
        int Lc = 0;
        #pragma unroll
        for (int dy = -1; dy <= 1; dy++) {
            int yy = Y + dy;
            unsigned char rin  = g_row_in[yy];
            unsigned char rout = g_row_out[yy];
            #pragma unroll
            for (int dx = -1; dx <= 1; dx++) {
                int xx = X + dx;
                size_t o = (size_t)yy * GNX + xx;
                int L = __ldg(lay + o);
                float m = (L == 2) ? 0.f : 1.f;
                float uu = __ldg(f0 + o) * m;
                float vv = __ldg(f1 + o) * m;
                float pp = __ldg(f2 + o) * m;
                if (xx == 0 && rin)        { uu = 3.f; vv = 0.f; }
                if (xx == GNX - 1 && rout) { pp = 0.f; }
                u[dy + 1][dx + 1] = uu;
                v[dy + 1][dx + 1] = vv;
                p[dy + 1][dx + 1] = pp;
                if (dy == 0 && dx == 0) Lc = L;
            }
        }

        const float h     = (float)(0.1 / 2047.0);
        const float inv_h = 1.0f / h;
        const float nu_h2 = 0.05f / (h * h);

        float Uc = u[1][1], Vc = v[1][1];
        float dxu = 0.5f * (u[1][2] - u[1][0]);
        float dyu = 0.5f * (u[2][1] - u[0][1]);
        float dxv = 0.5f * (v[1][2] - v[1][0]);
        float dyv = 0.5f * (v[2][1] - v[0][1]);
        float lapu = u[0][1] + u[2][1] + u[1][0] + u[1][2] - 4.0f * Uc;
        float lapv = v[0][1] + v[2][1] + v[1][0] + v[1][2] - 4.0f * Vc;
        float cont = dxu * inv_h + dyv * inv_h;

        int L = Lc;
        bool fx  = (L == 4) | (L == 8)  | (L == 11);
        bool bx  = (L == 6) | (L == 9)  | (L == 10);
        bool fy  = (L == 7) | (L == 10) | (L == 11);
        bool by  = (L == 5) | (L == 8)  | (L == 9);
        float dpx = fx ? (p[1][2] - p[1][1]) : (bx ? (p[1][1] - p[1][0]) : 0.5f * (p[1][2] - p[1][0]));
        float dpy = fy ? (p[0][1] - p[1][1]) : (by ? (p[1][1] - p[2][1]) : 0.5f * (p[2][1] - p[0][1]));

        float mu = Uc * dxu * inv_h + Vc * dyu * inv_h + dpx * inv_h - lapu * nu_h2;
        float mv = Uc * dxv * inv_h + Vc * dyv * inv_h + dpy * inv_h - lapv * nu_h2;

        float m = (L == 2) ? 0.f : 1.f;
        float r0 = m * mu, r1 = m * mv, r2 = m * cont;

        size_t li = (size_t)(Y - 1) * NNX + (X - 1);
        #pragma unroll
        for (int rep = 0; rep < 3; rep++) {
            out_loss[(size_t)(0 * 3 + rep) * NN + li] = r0;
            out_loss[(size_t)(1 * 3 + rep) * NN + li] = r1;
            out_loss[(size_t)(2 * 3 + rep) * NN + li] = r2;
        }
    }
}

extern "C" void kernel_launch(void* const* d_in, const int* in_sizes, int n_in,
                              void* d_out, int out_size) {
    const int*   layout = (const int*)d_in[0];
    const float* flow   = (const float*)d_in[1];
    const size_t NP = (size_t)GNX * GNY;
    const size_t NN = (size_t)NNX * NNX;

    const int*   lay = layout + NP;        // layout[0,1]
    const float* f0  = flow;
    const float* f1  = flow + NP;
    const float* f2  = flow + 2 * NP;

    float* out      = (float*)d_out;
    float* out_loss = out;
    float* out_mask = out_loss + 9 * NN;
    float* out_gbv  = out_mask + 3 * NP;

    static cudaStream_t s1 = 0, s2 = 0;
    static cudaEvent_t  ev_fork = 0, ev_j1 = 0, ev_j2 = 0;
    if (s1 == 0) {
        cudaStreamCreateWithFlags(&s1, cudaStreamNonBlocking);
        cudaStreamCreateWithFlags(&s2, cudaStreamNonBlocking);
        cudaEventCreateWithFlags(&ev_fork, cudaEventDisableTiming);
        cudaEventCreateWithFlags(&ev_j1, cudaEventDisableTiming);
        cudaEventCreateWithFlags(&ev_j2, cudaEventDisableTiming);
    }

    // fork all three concurrently
    cudaEventRecord(ev_fork, 0);
    cudaStreamWaitEvent(s1, ev_fork, 0);
    cudaStreamWaitEvent(s2, ev_fork, 0);

    dim3 block(32, 8);
    row_flags_kernel<<<GNY / 8, 256, 0, s1>>>(lay);
    mask_kernel<<<dim3(16, 256), block, 0, s2>>>(lay, out_mask, out_gbv);
    loss_kernel<<<dim3(16, 256), block>>>(lay, f0, f1, f2, out_loss);

    // join, then fix flag-dependent edges
    cudaEventRecord(ev_j1, s1);
    cudaEventRecord(ev_j2, s2);
    cudaStreamWaitEvent(0, ev_j1, 0);
    cudaStreamWaitEvent(0, ev_j2, 0);
    edge_fix_kernel<<<32, 256>>>(lay, f0, f1, f2, out_loss, out_mask, out_gbv);
}

// round 7
// speedup vs baseline: 1.0875x; 1.0875x over previous
#include <cuda_runtime.h>

// NSE_layer: fused NSE residual + BC-mask outputs, 2048x2048 grid.
// Output flat concat: loss (3,3,2046,2046) | mask (1,3,2048,2048) | gbv (2,1,3,2048,2048)
// Structure: flags -> (mask ∥ loss). Loss uses parity-shifted windows for STG.128 stores.

#define GNX 2048
#define GNY 2048
#define NNX 2046

__device__ unsigned char g_row_in[GNY];
__device__ unsigned char g_row_out[GNY];

// One block per row: 2 int4 loads/thread, single sync-or pair. 2048 blocks.
__global__ __launch_bounds__(256)
void row_flags_kernel(const int* __restrict__ lay) {
    int y = blockIdx.x;
    const int4* row = (const int4*)(lay + (size_t)y * GNX);   // 512 int4
    int4 a = __ldg(row + threadIdx.x);
    int4 b = __ldg(row + threadIdx.x + 256);
    int fin  = (a.x == 1) | (a.y == 1) | (a.z == 1) | (a.w == 1)
             | (b.x == 1) | (b.y == 1) | (b.z == 1) | (b.w == 1);
    int fout = (a.x == 3) | (a.y == 3) | (a.z == 3) | (a.w == 3)
             | (b.x == 3) | (b.y == 3) | (b.z == 3) | (b.w == 3);
    fin  = __syncthreads_or(fin);
    fout = __syncthreads_or(fout);
    if (threadIdx.x == 0) {
        g_row_in[y]  = (unsigned char)(fin  ? 1 : 0);
        g_row_out[y] = (unsigned char)(fout ? 1 : 0);
    }
}

// ---------------- mask + gbv kernel (reads flags, handles own edges) ----------------
__global__ __launch_bounds__(256)
void mask_kernel(const int* __restrict__ lay,
                 float* __restrict__ out_mask,
                 float* __restrict__ out_gbv)
{
    const size_t NP = (size_t)GNX * GNY;
    int k = blockIdx.x * 32 + threadIdx.x;      // 0..511
    int Y = blockIdx.y * 8  + threadIdx.y;      // 0..2047
    size_t idx = (size_t)Y * GNX + 4 * k;

    int4 L4 = __ldg((const int4*)(lay + idx));
    int Ls[4] = {L4.x, L4.y, L4.z, L4.w};
    unsigned char rin  = g_row_in[Y];
    unsigned char rout = g_row_out[Y];

    float gb0[4], gb1[4], gb2[4], gv0[4], mk0[4], mk1[4], mk2[4];
    #pragma unroll
    for (int j = 0; j < 4; j++) {
        int L = Ls[j];
        float base = (L == 2) ? 0.f : 1.f;
        float a0 = base, a1 = base, a2 = base, v0 = 0.f;
        int X = 4 * k + j;
        if (X == 0 && rin)        { a0 = 0.f; a1 = 0.f; v0 = 3.f; }
        if (X == GNX - 1 && rout) { a2 = 0.f; }
        float keep = (L > 3) ? 0.f : 1.f;
        float code = (L > 3) ? (float)L : 0.f;
        gb0[j] = a0; gb1[j] = a1; gb2[j] = a2; gv0[j] = v0;
        mk0[j] = a0 * keep + code;
        mk1[j] = a1 * keep + code;
        mk2[j] = a2 * keep + code;
    }

    __stcs((float4*)(out_mask + 0 * NP + idx), make_float4(mk0[0], mk0[1], mk0[2], mk0[3]));
    __stcs((float4*)(out_mask + 1 * NP + idx), make_float4(mk1[0], mk1[1], mk1[2], mk1[3]));
    __stcs((float4*)(out_mask + 2 * NP + idx), make_float4(mk2[0], mk2[1], mk2[2], mk2[3]));
    __stcs((float4*)(out_gbv + 0 * NP + idx), make_float4(gb0[0], gb0[1], gb0[2], gb0[3]));
    __stcs((float4*)(out_gbv + 1 * NP + idx), make_float4(gb1[0], gb1[1], gb1[2], gb1[3]));
    __stcs((float4*)(out_gbv + 2 * NP + idx), make_float4(gb2[0], gb2[1], gb2[2], gb2[3]));
    __stcs((float4*)(out_gbv + 3 * NP + idx), make_float4(gv0[0], gv0[1], gv0[2], gv0[3]));
    float4 z = make_float4(0.f, 0.f, 0.f, 0.f);
    __stcs((float4*)(out_gbv + 4 * NP + idx), z);
    __stcs((float4*)(out_gbv + 5 * NP + idx), z);
}

// ---------------- loss kernel: parity-shifted windows, STG.128 stores ----------------
// mode 0: float4 @x0 + float2 @x0+4   (window = x0..x0+5)
// mode 1: float2 @x0 + float4 @x0+2   (window = x0..x0+5)
// mode 2: float4 @x0 only             (window = x0..x0+3; pos 4,5 zero)
__device__ __forceinline__ void load_row_w(
    const float* __restrict__ f0, const float* __restrict__ f1,
    const float* __restrict__ f2, const int* __restrict__ lay,
    int r, int x0, int mode,
    float* u, float* v, float* p, int* lf_out)
{
    size_t off = (size_t)r * GNX + x0;
    float uf[6] = {0,0,0,0,0,0}, vf[6] = {0,0,0,0,0,0}, pf[6] = {0,0,0,0,0,0};
    int   lf[6] = {0,0,0,0,0,0};
    if (mode == 0) {
        float4 a0 = __ldg((const float4*)(f0 + off));
        float4 a1 = __ldg((const float4*)(f1 + off));
        float4 a2 = __ldg((const float4*)(f2 + off));
        int4   al = __ldg((const int4*)(lay + off));
        float2 b0 = __ldg((const float2*)(f0 + off + 4));
        float2 b1 = __ldg((const float2*)(f1 + off + 4));
        float2 b2 = __ldg((const float2*)(f2 + off + 4));
        int2   bl = __ldg((const int2*)(lay + off + 4));
        uf[0]=a0.x; uf[1]=a0.y; uf[2]=a0.z; uf[3]=a0.w; uf[4]=b0.x; uf[5]=b0.y;
        vf[0]=a1.x; vf[1]=a1.y; vf[2]=a1.z; vf[3]=a1.w; vf[4]=b1.x; vf[5]=b1.y;
        pf[0]=a2.x; pf[1]=a2.y; pf[2]=a2.z; pf[3]=a2.w; pf[4]=b2.x; pf[5]=b2.y;
        lf[0]=al.x; lf[1]=al.y; lf[2]=al.z; lf[3]=al.w; lf[4]=bl.x; lf[5]=bl.y;
    } else if (mode == 1) {
        float2 b0 = __ldg((const float2*)(f0 + off));
        float2 b1 = __ldg((const float2*)(f1 + off));
        float2 b2 = __ldg((const float2*)(f2 + off));
        int2   bl = __ldg((const int2*)(lay + off));
        float4 a0 = __ldg((const float4*)(f0 + off + 2));
        float4 a1 = __ldg((const float4*)(f1 + off + 2));
        float4 a2 = __ldg((const float4*)(f2 + off + 2));
        int4   al = __ldg((const int4*)(lay + off + 2));
        uf[0]=b0.x; uf[1]=b0.y; uf[2]=a0.x; uf[3]=a0.y; uf[4]=a0.z; uf[5]=a0.w;
        vf[0]=b1.x; vf[1]=b1.y; vf[2]=a1.x; vf[3]=a1.y; vf[4]=a1.z; vf[5]=a1.w;
        pf[0]=b2.x; pf[1]=b2.y; pf[2]=a2.x; pf[3]=a2.y; pf[4]=a2.z; pf[5]=a2.w;
        lf[0]=bl.x; lf[1]=bl.y; lf[2]=al.x; lf[3]=al.y; lf[4]=al.z; lf[5]=al.w;
    } else {
        float4 a0 = __ldg((const float4*)(f0 + off));
        float4 a1 = __ldg((const float4*)(f1 + off));
        float4 a2 = __ldg((const float4*)(f2 + off));
        int4   al = __ldg((const int4*)(lay + off));
        uf[0]=a0.x; uf[1]=a0.y; uf[2]=a0.z; uf[3]=a0.w;
        vf[0]=a1.x; vf[1]=a1.y; vf[2]=a1.z; vf[3]=a1.w;
        pf[0]=a2.x; pf[1]=a2.y; pf[2]=a2.z; pf[3]=a2.w;
        lf[0]=al.x; lf[1]=al.y; lf[2]=al.z; lf[3]=al.w;
    }
    unsigned char rin  = g_row_in[r];
    unsigned char rout = g_row_out[r];
    #pragma unroll
    for (int i = 0; i < 6; i++) {
        int x = x0 + i;
        float m = (lf[i] == 2) ? 0.f : 1.f;
        float uu = uf[i] * m;
        float vv = vf[i] * m;
        float pp = pf[i] * m;
        if (x == 0 && rin)        { uu = 3.f; vv = 0.f; }
        if (x == GNX - 1 && rout) { pp = 0.f; }
        u[i] = uu; v[i] = vv; p[i] = pp;
        if (lf_out) lf_out[i] = lf[i];
    }
}

__global__ __launch_bounds__(256)
void loss_kernel(const int* __restrict__ lay,
                 const float* __restrict__ f0,
                 const float* __restrict__ f1,
                 const float* __restrict__ f2,
                 float* __restrict__ out_loss)
{
    const size_t NN = (size_t)NNX * NNX;
    int k = blockIdx.x * 32 + threadIdx.x;        // 0..511
    int Y = blockIdx.y * 8  + threadIdx.y + 1;    // 1..2048
    if (Y > GNY - 2) return;

    const int s = (Y & 1) ? 0 : 2;                // parity shift
    const bool last = (k == 511);
    // last thread: s==0 -> tail pixels X=2045,2046 (mode 2 @2044);
    //              s==2 -> leftover pixels X=1,2  (mode 2 @0)
    int  x0, mode;
    if (!last)        { x0 = 4 * k + s; mode = (s == 0) ? 0 : 1; }
    else if (s == 0)  { x0 = 2044;      mode = 2; }
    else              { x0 = 0;         mode = 2; }

    float un[6], vn[6], pn[6];
    float uc[6], vc[6], pc[6];
    float us[6], vs[6], ps[6];
    int   lc[6];
    load_row_w(f0, f1, f2, lay, Y - 1, x0, mode, un, vn, pn, (int*)0);
    load_row_w(f0, f1, f2, lay, Y,     x0, mode, uc, vc, pc, lc);
    load_row_w(f0, f1, f2, lay, Y + 1, x0, mode, us, vs, ps, (int*)0);

    const float h     = (float)(0.1 / 2047.0);
    const float inv_h = 1.0f / h;
    const float nu_h2 = 0.05f / (h * h);

    float r0[4], r1[4], r2[4];
    #pragma unroll
    for (int j = 0; j < 4; j++) {
        int   L   = lc[j + 1];
        float Uc  = uc[j + 1], Vc = vc[j + 1];
        float dxu = 0.5f * (uc[j + 2] - uc[j]);
        float dyu = 0.5f * (us[j + 1] - un[j + 1]);
        float dxv = 0.5f * (vc[j + 2] - vc[j]);
        float dyv = 0.5f * (vs[j + 1] - vn[j + 1]);
        float lapu = un[j + 1] + us[j + 1] + uc[j] + uc[j + 2] - 4.0f * Uc;
        float lapv = vn[j + 1] + vs[j + 1] + vc[j] + vc[j + 2] - 4.0f * Vc;
        float cont = dxu * inv_h + dyv * inv_h;

        bool fx  = (L == 4) | (L == 8)  | (L == 11);
        bool bx  = (L == 6) | (L == 9)  | (L == 10);
        bool fy  = (L == 7) | (L == 10) | (L == 11);
        bool by  = (L == 5) | (L == 8)  | (L == 9);
        float dpx = fx ? (pc[j + 2] - pc[j + 1]) : (bx ? (pc[j + 1] - pc[j]) : 0.5f * (pc[j + 2] - pc[j]));
        float dpy = fy ? (pn[j + 1] - pc[j + 1]) : (by ? (pc[j + 1] - ps[j + 1]) : 0.5f * (ps[j + 1] - pn[j + 1]));

        float mu = Uc * dxu * inv_h + Vc * dyu * inv_h + dpx * inv_h - lapu * nu_h2;
        float mv = Uc * dxv * inv_h + Vc * dyv * inv_h + dpy * inv_h - lapv * nu_h2;

        float m = (L == 2) ? 0.f : 1.f;
        r0[j] = m * mu; r1[j] = m * mv; r2[j] = m * cont;
    }

    size_t li = (size_t)(Y - 1) * NNX + x0;   // pixel X = x0 + 1 + j -> li + j
    if (mode != 2) {
        // li % 4 == 0 by construction -> STG.128
        float4 q0 = make_float4(r0[0], r0[1], r0[2], r0[3]);
        float4 q1 = make_float4(r1[0], r1[1], r1[2], r1[3]);
        float4 q2 = make_float4(r2[0], r2[1], r2[2], r2[3]);
        #pragma unroll
        for (int rep = 0; rep < 3; rep++) {
            __stcs((float4*)(out_loss + (size_t)(0 * 3 + rep) * NN + li), q0);
            __stcs((float4*)(out_loss + (size_t)(1 * 3 + rep) * NN + li), q1);
            __stcs((float4*)(out_loss + (size_t)(2 * 3 + rep) * NN + li), q2);
        }
    } else {
        // two pixels only (j = 0,1); li is even -> STG.64
        float2 q0 = make_float2(r0[0], r0[1]);
        float2 q1 = make_float2(r1[0], r1[1]);
        float2 q2 = make_float2(r2[0], r2[1]);
        #pragma unroll
        for (int rep = 0; rep < 3; rep++) {
            __stcs((float2*)(out_loss + (size_t)(0 * 3 + rep) * NN + li), q0);
            __stcs((float2*)(out_loss + (size_t)(1 * 3 + rep) * NN + li), q1);
            __stcs((float2*)(out_loss + (size_t)(2 * 3 + rep) * NN + li), q2);
        }
    }
}

extern "C" void kernel_launch(void* const* d_in, const int* in_sizes, int n_in,
                              void* d_out, int out_size) {
    const int*   layout = (const int*)d_in[0];
    const float* flow   = (const float*)d_in[1];
    const size_t NP = (size_t)GNX * GNY;
    const size_t NN = (size_t)NNX * NNX;

    const int*   lay = layout + NP;        // layout[0,1]
    const float* f0  = flow;
    const float* f1  = flow + NP;
    const float* f2  = flow + 2 * NP;

    float* out      = (float*)d_out;
    float* out_loss = out;
    float* out_mask = out_loss + 9 * NN;
    float* out_gbv  = out_mask + 3 * NP;

    static cudaStream_t s_side = 0;
    static cudaEvent_t  ev_fork = 0, ev_join = 0;
    if (s_side == 0) {
        cudaStreamCreateWithFlags(&s_side, cudaStreamNonBlocking);
        cudaEventCreateWithFlags(&ev_fork, cudaEventDisableTiming);
        cudaEventCreateWithFlags(&ev_join, cudaEventDisableTiming);
    }

    row_flags_kernel<<<GNY, 256>>>(lay);

    // fork: mask on side stream, loss on main stream, both after flags
    cudaEventRecord(ev_fork, 0);
    cudaStreamWaitEvent(s_side, ev_fork, 0);

    dim3 block(32, 8);
    mask_kernel<<<dim3(16, 256), block, 0, s_side>>>(lay, out_mask, out_gbv);
    loss_kernel<<<dim3(16, 256), block>>>(lay, f0, f1, f2, out_loss);

    cudaEventRecord(ev_join, s_side);
    cudaStreamWaitEvent(0, ev_join, 0);
}

// round 8
// speedup vs baseline: 1.1932x; 1.0972x over previous
#include <cuda_runtime.h>

// NSE_layer: fused NSE residual + BC-mask outputs, 2048x2048 grid.
// Output flat concat: loss (3,3,2046,2046) | mask (1,3,2048,2048) | gbv (2,1,3,2048,2048)
// Concurrency: [flags+mask_edges -> loss_edge] || [mask_bulk] || [loss_bulk]; disjoint writes.

#define GNX 2048
#define GNY 2048
#define NNX 2046

__device__ unsigned char g_row_in[GNY];
__device__ unsigned char g_row_out[GNY];

// One block per row: computes flags AND writes the flag-dependent mask/gbv
// edge columns (X=0 by thread 0, X=2047 by thread 255) using in-register lay values.
__global__ __launch_bounds__(256)
void flags_kernel(const int* __restrict__ lay,
                  float* __restrict__ out_mask,
                  float* __restrict__ out_gbv)
{
    const size_t NP = (size_t)GNX * GNY;
    int y = blockIdx.x;
    const int4* row = (const int4*)(lay + (size_t)y * GNX);   // 512 int4
    int4 a = __ldg(row + threadIdx.x);
    int4 b = __ldg(row + threadIdx.x + 256);
    int fin  = (a.x == 1) | (a.y == 1) | (a.z == 1) | (a.w == 1)
             | (b.x == 1) | (b.y == 1) | (b.z == 1) | (b.w == 1);
    int fout = (a.x == 3) | (a.y == 3) | (a.z == 3) | (a.w == 3)
             | (b.x == 3) | (b.y == 3) | (b.z == 3) | (b.w == 3);
    fin  = __syncthreads_or(fin);
    fout = __syncthreads_or(fout);

    if (threadIdx.x == 0) {
        g_row_in[y]  = (unsigned char)(fin  ? 1 : 0);
        g_row_out[y] = (unsigned char)(fout ? 1 : 0);
        // mask/gbv at X = 0 (uses lay[y][0] = a.x)
        int L = a.x;
        float base = (L == 2) ? 0.f : 1.f;
        float gb0 = fin ? 0.f : base;
        float gb1 = fin ? 0.f : base;
        float gb2 = base;
        float gv0 = fin ? 3.f : 0.f;
        float keep = (L > 3) ? 0.f : 1.f;
        float code = (L > 3) ? (float)L : 0.f;
        size_t idx = (size_t)y * GNX;
        out_mask[0 * NP + idx] = gb0 * keep + code;
        out_mask[1 * NP + idx] = gb1 * keep + code;
        out_mask[2 * NP + idx] = gb2 * keep + code;
        out_gbv[0 * NP + idx] = gb0;
        out_gbv[1 * NP + idx] = gb1;
        out_gbv[2 * NP + idx] = gb2;
        out_gbv[3 * NP + idx] = gv0;
    }
    if (threadIdx.x == 255) {
        // mask/gbv at X = 2047 (uses lay[y][2047] = b.w)
        int L = b.w;
        float base = (L == 2) ? 0.f : 1.f;
        float gb0 = base, gb1 = base;
        float gb2 = fout ? 0.f : base;
        float keep = (L > 3) ? 0.f : 1.f;
        float code = (L > 3) ? (float)L : 0.f;
        size_t idx = (size_t)y * GNX + (GNX - 1);
        out_mask[0 * NP + idx] = gb0 * keep + code;
        out_mask[1 * NP + idx] = gb1 * keep + code;
        out_mask[2 * NP + idx] = gb2 * keep + code;
        out_gbv[0 * NP + idx] = gb0;
        out_gbv[1 * NP + idx] = gb1;
        out_gbv[2 * NP + idx] = gb2;
        out_gbv[3 * NP + idx] = 0.f;
    }
}

// ---------------- mask_bulk: flag-free; skips X=0/2047 on flag-dependent planes ----------------
__device__ __forceinline__ void store_plane_skip(float* __restrict__ base, size_t idx,
                                                 float4 val, int k)
{
    if (k == 0) {
        __stcs(base + idx + 1, val.y);
        __stcs((float2*)(base + idx + 2), make_float2(val.z, val.w));
    } else if (k == 511) {
        __stcs((float2*)(base + idx), make_float2(val.x, val.y));
        __stcs(base + idx + 2, val.z);
    } else {
        __stcs((float4*)(base + idx), val);
    }
}

__global__ __launch_bounds__(256)
void mask_bulk_kernel(const int* __restrict__ lay,
                      float* __restrict__ out_mask,
                      float* __restrict__ out_gbv)
{
    const size_t NP = (size_t)GNX * GNY;
    int k = blockIdx.x * 32 + threadIdx.x;      // 0..511
    int Y = blockIdx.y * 8  + threadIdx.y;      // 0..2047
    size_t idx = (size_t)Y * GNX + 4 * k;

    int4 L4 = __ldg((const int4*)(lay + idx));
    int Ls[4] = {L4.x, L4.y, L4.z, L4.w};

    float mk[4], gb[4];
    #pragma unroll
    for (int j = 0; j < 4; j++) {
        int L = Ls[j];
        float base = (L == 2) ? 0.f : 1.f;
        float keep = (L > 3) ? 0.f : 1.f;
        float code = (L > 3) ? (float)L : 0.f;
        gb[j] = base;
        mk[j] = base * keep + code;
    }
    float4 mkv = make_float4(mk[0], mk[1], mk[2], mk[3]);
    float4 gbv = make_float4(gb[0], gb[1], gb[2], gb[3]);
    float4 z   = make_float4(0.f, 0.f, 0.f, 0.f);

    // flag-dependent planes: skip edge columns (written by flags_kernel)
    store_plane_skip(out_mask + 0 * NP, idx, mkv, k);
    store_plane_skip(out_mask + 1 * NP, idx, mkv, k);
    store_plane_skip(out_mask + 2 * NP, idx, mkv, k);
    store_plane_skip(out_gbv + 0 * NP, idx, gbv, k);
    store_plane_skip(out_gbv + 1 * NP, idx, gbv, k);
    store_plane_skip(out_gbv + 2 * NP, idx, gbv, k);
    store_plane_skip(out_gbv + 3 * NP, idx, z,   k);
    // always-zero planes: full width, flag-independent
    __stcs((float4*)(out_gbv + 4 * NP + idx), z);
    __stcs((float4*)(out_gbv + 5 * NP + idx), z);
}

// ---------------- loss_bulk: R4 scheme, flag-free, skips pixels X=1 and X=2046 ----------------
__device__ __forceinline__ void load_uvp_row_nf(
    const float* __restrict__ f0, const float* __restrict__ f1,
    const float* __restrict__ f2, const int* __restrict__ lay,
    int r, int xv, bool tail,
    float* u, float* v, float* p, int* lf_out)
{
    size_t off = (size_t)r * GNX + xv;
    float4 ua = __ldg((const float4*)(f0 + off));
    float4 va = __ldg((const float4*)(f1 + off));
    float4 pa = __ldg((const float4*)(f2 + off));
    int4   la = __ldg((const int4*)(lay + off));
    float u4 = 0.f, u5 = 0.f, v4 = 0.f, v5 = 0.f, p4 = 0.f, p5 = 0.f;
    int   l4 = 0, l5 = 0;
    if (!tail) {
        float4 ub = __ldg((const float4*)(f0 + off + 4));
        float4 vb = __ldg((const float4*)(f1 + off + 4));
        float4 pb = __ldg((const float4*)(f2 + off + 4));
        int4   lb = __ldg((const int4*)(lay + off + 4));
        u4 = ub.x; u5 = ub.y; v4 = vb.x; v5 = vb.y; p4 = pb.x; p5 = pb.y;
        l4 = lb.x; l5 = lb.y;
    }
    float uf[6] = {ua.x, ua.y, ua.z, ua.w, u4, u5};
    float vf[6] = {va.x, va.y, va.z, va.w, v4, v5};
    float pf[6] = {pa.x, pa.y, pa.z, pa.w, p4, p5};
    int   lf[6] = {la.x, la.y, la.z, la.w, l4, l5};
    #pragma unroll
    for (int i = 0; i < 6; i++) {
        float m = (lf[i] == 2) ? 0.f : 1.f;
        u[i] = uf[i] * m;
        v[i] = vf[i] * m;
        p[i] = pf[i] * m;
        if (lf_out) lf_out[i] = lf[i];
    }
}

__global__ __launch_bounds__(256)
void loss_bulk_kernel(const int* __restrict__ lay,
                      const float* __restrict__ f0,
                      const float* __restrict__ f1,
                      const float* __restrict__ f2,
                      float* __restrict__ out_loss)
{
    const size_t NN = (size_t)NNX * NNX;
    int k = blockIdx.x * 32 + threadIdx.x;        // 0..511
    int Y = blockIdx.y * 8  + threadIdx.y + 1;    // 1..2048
    if (Y > GNY - 2) return;
    bool tail = (k == 511);
    int  xv   = 4 * k;                            // pixels X = xv+1 .. xv+4 (tail: 2045,2046)

    float un[6], vn[6], pn[6];
    float uc[6], vc[6], pc[6];
    float us[6], vs[6], ps[6];
    int   lc[6];
    load_uvp_row_nf(f0, f1, f2, lay, Y - 1, xv, tail, un, vn, pn, (int*)0);
    load_uvp_row_nf(f0, f1, f2, lay, Y,     xv, tail, uc, vc, pc, lc);
    load_uvp_row_nf(f0, f1, f2, lay, Y + 1, xv, tail, us, vs, ps, (int*)0);

    const float h     = (float)(0.1 / 2047.0);
    const float inv_h = 1.0f / h;
    const float nu_h2 = 0.05f / (h * h);

    float r0[4], r1[4], r2[4];
    #pragma unroll
    for (int j = 0; j < 4; j++) {
        int   L   = lc[j + 1];
        float Uc  = uc[j + 1], Vc = vc[j + 1];
        float dxu = 0.5f * (uc[j + 2] - uc[j]);
        float dyu = 0.5f * (us[j + 1] - un[j + 1]);
        float dxv = 0.5f * (vc[j + 2] - vc[j]);
        float dyv = 0.5f * (vs[j + 1] - vn[j + 1]);
        float lapu = un[j + 1] + us[j + 1] + uc[j] + uc[j + 2] - 4.0f * Uc;
        float lapv = vn[j + 1] + vs[j + 1] + vc[j] + vc[j + 2] - 4.0f * Vc;
        float cont = dxu * inv_h + dyv * inv_h;

        bool fx  = (L == 4) | (L == 8)  | (L == 11);
        bool bx  = (L == 6) | (L == 9)  | (L == 10);
        bool fy  = (L == 7) | (L == 10) | (L == 11);
        bool by  = (L == 5) | (L == 8)  | (L == 9);
        float dpx = fx ? (pc[j + 2] - pc[j + 1]) : (bx ? (pc[j + 1] - pc[j]) : 0.5f * (pc[j + 2] - pc[j]));
        float dpy = fy ? (pn[j + 1] - pc[j + 1]) : (by ? (pc[j + 1] - ps[j + 1]) : 0.5f * (ps[j + 1] - pn[j + 1]));

        float mu = Uc * dxu * inv_h + Vc * dyu * inv_h + dpx * inv_h - lapu * nu_h2;
        float mv = Uc * dxv * inv_h + Vc * dyv * inv_h + dpy * inv_h - lapv * nu_h2;

        float m = (L == 2) ? 0.f : 1.f;
        r0[j] = m * mu; r1[j] = m * mv; r2[j] = m * cont;
    }

    size_t li = (size_t)(Y - 1) * NNX + 4 * k;    // even
    #pragma unroll
    for (int rep = 0; rep < 3; rep++) {
        float* p0 = out_loss + (size_t)(0 * 3 + rep) * NN + li;
        float* p1 = out_loss + (size_t)(1 * 3 + rep) * NN + li;
        float* p2 = out_loss + (size_t)(2 * 3 + rep) * NN + li;
        if (k == 0) {
            // skip pixel X=1 (j=0); write j=1 scalar, (j=2,j=3) float2
            __stcs(p0 + 1, r0[1]); __stcs((float2*)(p0 + 2), make_float2(r0[2], r0[3]));
            __stcs(p1 + 1, r1[1]); __stcs((float2*)(p1 + 2), make_float2(r1[2], r1[3]));
            __stcs(p2 + 1, r2[1]); __stcs((float2*)(p2 + 2), make_float2(r2[2], r2[3]));
        } else if (tail) {
            // pixels X=2045 (j=0) keep, X=2046 (j=1) skip
            __stcs(p0, r0[0]);
            __stcs(p1, r1[0]);
            __stcs(p2, r2[0]);
        } else {
            __stcs((float2*)p0, make_float2(r0[0], r0[1]));
            __stcs((float2*)(p0 + 2), make_float2(r0[2], r0[3]));
            __stcs((float2*)p1, make_float2(r1[0], r1[1]));
            __stcs((float2*)(p1 + 2), make_float2(r1[2], r1[3]));
            __stcs((float2*)p2, make_float2(r2[0], r2[1]));
            __stcs((float2*)(p2 + 2), make_float2(r2[2], r2[3]));
        }
    }
}

// ---------------- loss_edge: pixels X=1 and X=2046, rows 1..2046 (needs flags) ----------------
__global__ __launch_bounds__(256)
void loss_edge_kernel(const int* __restrict__ lay,
                      const float* __restrict__ f0,
                      const float* __restrict__ f1,
                      const float* __restrict__ f2,
                      float* __restrict__ out_loss)
{
    const size_t NN = (size_t)NNX * NNX;
    int t = blockIdx.x * blockDim.x + threadIdx.x;
    int side = t & 1;
    int Y = (t >> 1) + 1;
    if (Y > GNY - 2) return;
    int X = side ? (GNX - 2) : 1;

    float u[3][3], v[3][3], p[3][3];
    int Lc = 0;
    #pragma unroll
    for (int dy = -1; dy <= 1; dy++) {
        int yy = Y + dy;
        unsigned char rin  = g_row_in[yy];
        unsigned char rout = g_row_out[yy];
        #pragma unroll
        for (int dx = -1; dx <= 1; dx++) {
            int xx = X + dx;
            size_t o = (size_t)yy * GNX + xx;
            int L = __ldg(lay + o);
            float m = (L == 2) ? 0.f : 1.f;
            float uu = __ldg(f0 + o) * m;
            float vv = __ldg(f1 + o) * m;
            float pp = __ldg(f2 + o) * m;
            if (xx == 0 && rin)        { uu = 3.f; vv = 0.f; }
            if (xx == GNX - 1 && rout) { pp = 0.f; }
            u[dy + 1][dx + 1] = uu;
            v[dy + 1][dx + 1] = vv;
            p[dy + 1][dx + 1] = pp;
            if (dy == 0 && dx == 0) Lc = L;
        }
    }

    const float h     = (float)(0.1 / 2047.0);
    const float inv_h = 1.0f / h;
    const float nu_h2 = 0.05f / (h * h);

    float Uc = u[1][1], Vc = v[1][1];
    float dxu = 0.5f * (u[1][2] - u[1][0]);
    float dyu = 0.5f * (u[2][1] - u[0][1]);
    float dxv = 0.5f * (v[1][2] - v[1][0]);
    float dyv = 0.5f * (v[2][1] - v[0][1]);
    float lapu = u[0][1] + u[2][1] + u[1][0] + u[1][2] - 4.0f * Uc;
    float lapv = v[0][1] + v[2][1] + v[1][0] + v[1][2] - 4.0f * Vc;
    float cont = dxu * inv_h + dyv * inv_h;

    int L = Lc;
    bool fx  = (L == 4) | (L == 8)  | (L == 11);
    bool bx  = (L == 6) | (L == 9)  | (L == 10);
    bool fy  = (L == 7) | (L == 10) | (L == 11);
    bool by  = (L == 5) | (L == 8)  | (L == 9);
    float dpx = fx ? (p[1][2] - p[1][1]) : (bx ? (p[1][1] - p[1][0]) : 0.5f * (p[1][2] - p[1][0]));
    float dpy = fy ? (p[0][1] - p[1][1]) : (by ? (p[1][1] - p[2][1]) : 0.5f * (p[2][1] - p[0][1]));

    float mu = Uc * dxu * inv_h + Vc * dyu * inv_h + dpx * inv_h - lapu * nu_h2;
    float mv = Uc * dxv * inv_h + Vc * dyv * inv_h + dpy * inv_h - lapv * nu_h2;

    float m = (L == 2) ? 0.f : 1.f;
    float r0 = m * mu, r1 = m * mv, r2 = m * cont;

    size_t li = (size_t)(Y - 1) * NNX + (X - 1);
    #pragma unroll
    for (int rep = 0; rep < 3; rep++) {
        out_loss[(size_t)(0 * 3 + rep) * NN + li] = r0;
        out_loss[(size_t)(1 * 3 + rep) * NN + li] = r1;
        out_loss[(size_t)(2 * 3 + rep) * NN + li] = r2;
    }
}

extern "C" void kernel_launch(void* const* d_in, const int* in_sizes, int n_in,
                              void* d_out, int out_size) {
    const int*   layout = (const int*)d_in[0];
    const float* flow   = (const float*)d_in[1];
    const size_t NP = (size_t)GNX * GNY;
    const size_t NN = (size_t)NNX * NNX;

    const int*   lay = layout + NP;        // layout[0,1]
    const float* f0  = flow;
    const float* f1  = flow + NP;
    const float* f2  = flow + 2 * NP;

    float* out      = (float*)d_out;
    float* out_loss = out;
    float* out_mask = out_loss + 9 * NN;
    float* out_gbv  = out_mask + 3 * NP;

    static cudaStream_t s1 = 0, s2 = 0;
    static cudaEvent_t  ev_fork = 0, ev_j1 = 0, ev_j2 = 0;
    if (s1 == 0) {
        cudaStreamCreateWithFlags(&s1, cudaStreamNonBlocking);
        cudaStreamCreateWithFlags(&s2, cudaStreamNonBlocking);
        cudaEventCreateWithFlags(&ev_fork, cudaEventDisableTiming);
        cudaEventCreateWithFlags(&ev_j1, cudaEventDisableTiming);
        cudaEventCreateWithFlags(&ev_j2, cudaEventDisableTiming);
    }

    cudaEventRecord(ev_fork, 0);
    cudaStreamWaitEvent(s1, ev_fork, 0);
    cudaStreamWaitEvent(s2, ev_fork, 0);

    dim3 block(32, 8);
    // chain on s1: flags (+ mask/gbv edge columns) -> loss edge pixels
    flags_kernel<<<GNY, 256, 0, s1>>>(lay, out_mask, out_gbv);
    loss_edge_kernel<<<16, 256, 0, s1>>>(lay, f0, f1, f2, out_loss);
    // bulk kernels, flag-free
    mask_bulk_kernel<<<dim3(16, 256), block, 0, s2>>>(lay, out_mask, out_gbv);
    loss_bulk_kernel<<<dim3(16, 256), block>>>(lay, f0, f1, f2, out_loss);

    cudaEventRecord(ev_j1, s1);
    cudaEventRecord(ev_j2, s2);
    cudaStreamWaitEvent(0, ev_j1, 0);
    cudaStreamWaitEvent(0, ev_j2, 0);
}